// round 4
// baseline (speedup 1.0000x reference)
#include <cuda_runtime.h>
#include <cuda_bf16.h>

// firing_model: next = -prev + tanh(prev @ x) from prev = 0 -> identically
// zero trajectory (tanh(0) = 0 exactly in fp32). Output [499800, 69] is all
// zeros -> pure 138 MB zero-fill of d_out. HBM-write bound.
//
// R4: continue the R3 axis — 4 contiguous .cs STG.128 per thread, exact
// cover. Each block covers 16 KB contiguous (good DRAM page locality),
// ~8.4k blocks. R3 measured 6.86 TB/s; this targets the ~7.2 TB/s write
// ceiling.

#define FILL_THREADS 256
#define F4_PER_THREAD 4   // each block covers FILL_THREADS * 4 float4s = 16 KB

__global__ void __launch_bounds__(FILL_THREADS)
firing_model_zero_fill4(float4* __restrict__ out, long long n4) {
    long long base = (long long)blockIdx.x * (FILL_THREADS * F4_PER_THREAD)
                   + threadIdx.x;
    const float4 z = make_float4(0.0f, 0.0f, 0.0f, 0.0f);

#pragma unroll
    for (int k = 0; k < F4_PER_THREAD; k++) {
        long long i = base + (long long)k * FILL_THREADS;
        if (i < n4) __stcs(&out[i], z);
    }
}

__global__ void firing_model_zero_fill_tail(float* __restrict__ out,
                                            long long start, long long n) {
    long long i = start + (long long)blockIdx.x * blockDim.x + threadIdx.x;
    if (i < n) {
        out[i] = 0.0f;
    }
}

extern "C" void kernel_launch(void* const* d_in, const int* in_sizes, int n_in,
                              void* d_out, int out_size) {
    (void)d_in; (void)in_sizes; (void)n_in;

    float* out = (float*)d_out;
    long long n  = (long long)out_size;   // 34,486,200 floats expected
    long long n4 = n >> 2;                // 8,621,550 float4s (exact for this shape)
    long long tail_start = n4 << 2;

    if (n4 > 0) {
        long long per_block = FILL_THREADS * F4_PER_THREAD;
        long long blocks = (n4 + per_block - 1) / per_block;   // ~8,420
        firing_model_zero_fill4<<<(unsigned int)blocks, FILL_THREADS>>>(
            (float4*)out, n4);
    }
    if (tail_start < n) {  // not taken for this shape; defensive
        long long tail = n - tail_start;
        int blocks = (int)((tail + 255) / 256);
        firing_model_zero_fill_tail<<<blocks, 256>>>(out, tail_start, n);
    }
}